// round 1
// baseline (speedup 1.0000x reference)
#include <cuda_runtime.h>
#include <math.h>

#define BQ 4
#define SQ 2048
#define WW 768
#define HH 12
#define DD 64

// Scratch (device globals: allocation-free contract)
__device__ float g_q[(size_t)BQ*HH*SQ*DD];
__device__ float g_k[(size_t)BQ*HH*SQ*DD];
__device__ float g_v[(size_t)BQ*HH*SQ*DD];
__device__ float g_ctx[(size_t)BQ*SQ*WW];

// ---------------------------------------------------------------------------
// QKV projection: for each (b,h,mat) compute C[S x D] = x[b] (S x W) @ Wm[h] (W x D) + bias
// BM=128, BN=64, BK=16, 128 threads, 8x8 per-thread tile, interleaved columns.
// ---------------------------------------------------------------------------
__global__ __launch_bounds__(128) void qkv_kernel(
    const float* __restrict__ x,
    const float* __restrict__ Wq, const float* __restrict__ Wk, const float* __restrict__ Wv,
    const float* __restrict__ bq, const float* __restrict__ bk, const float* __restrict__ bv)
{
    __shared__ float As[16][128];
    __shared__ float Bs[16][64];

    const int mat = blockIdx.z;
    const float* Wm = (mat == 0) ? Wq : (mat == 1) ? Wk : Wv;
    const float* bm = (mat == 0) ? bq : (mat == 1) ? bk : bv;
    float* Om       = (mat == 0) ? g_q : (mat == 1) ? g_k : g_v;

    const int bh = blockIdx.y;
    const int b = bh / HH, h = bh % HH;
    const int m0 = blockIdx.x * 128;

    const float* A  = x  + (size_t)b * SQ * WW;
    const float* Bw = Wm + (size_t)h * WW * DD;

    const int tid = threadIdx.x;
    const int rg = tid >> 3, cg = tid & 7;
    const int r0 = rg * 8;

    float acc[8][8];
#pragma unroll
    for (int i = 0; i < 8; i++)
#pragma unroll
        for (int j = 0; j < 8; j++) acc[i][j] = 0.0f;

    for (int k0 = 0; k0 < WW; k0 += 16) {
        // A tile: 128 x 16
#pragma unroll
        for (int t = 0; t < 16; t++) {
            int i = tid + t * 128;
            int m = i >> 4, kk = i & 15;
            As[kk][m] = A[(size_t)(m0 + m) * WW + k0 + kk];
        }
        // B tile: 16 x 64
#pragma unroll
        for (int t = 0; t < 8; t++) {
            int i = tid + t * 128;
            int kk = i >> 6, n = i & 63;
            Bs[kk][n] = Bw[(size_t)(k0 + kk) * DD + n];
        }
        __syncthreads();
#pragma unroll
        for (int kk = 0; kk < 16; kk++) {
            float a[8], bb[8];
#pragma unroll
            for (int i = 0; i < 8; i++) a[i] = As[kk][r0 + i];
#pragma unroll
            for (int j = 0; j < 8; j++) bb[j] = Bs[kk][cg + 8 * j];
#pragma unroll
            for (int i = 0; i < 8; i++)
#pragma unroll
                for (int j = 0; j < 8; j++) acc[i][j] += a[i] * bb[j];
        }
        __syncthreads();
    }

    float* O = Om + ((size_t)bh * SQ + m0) * DD;
#pragma unroll
    for (int i = 0; i < 8; i++)
#pragma unroll
        for (int j = 0; j < 8; j++) {
            int n = cg + 8 * j;
            O[(size_t)(r0 + i) * DD + n] = acc[i][j] + bm[h * DD + n];
        }
}

// ---------------------------------------------------------------------------
// Flash attention (fp32, online softmax). One block = 64 query rows of one (b,h).
// 128 threads: rg = tid/8 owns 4 rows, cg = tid%8 owns 8 interleaved columns.
// Shared: Qs/KVs/Ps each 64x64 with skewed addressing -> bank-conflict-free,
// total exactly 48 KB dynamic smem (default limit, no opt-in).
// ---------------------------------------------------------------------------
#define SKEW(r, c) (((r) << 6) + (((c) + (r)) & 63))

__global__ __launch_bounds__(128) void attn_kernel()
{
    extern __shared__ float sm[];
    float* Qs  = sm;            // 4096 floats
    float* KVs = sm + 4096;     // 4096 floats (K tile, then reused for V tile)
    float* Ps  = sm + 8192;     // 4096 floats

    const int bh = blockIdx.y;
    const int m0 = blockIdx.x * 64;
    const float* Qg = g_q + ((size_t)bh * SQ + m0) * DD;
    const float* Kg = g_k + (size_t)bh * SQ * DD;
    const float* Vg = g_v + (size_t)bh * SQ * DD;

    const int tid = threadIdx.x;
    const int rg = tid >> 3, cg = tid & 7;
    const int r0 = rg * 4;

    // Load Q tile (64 x 64), skewed
#pragma unroll
    for (int t = 0; t < 32; t++) {
        int i = tid + t * 128;
        int r = i >> 6, c = i & 63;
        Qs[SKEW(r, c)] = Qg[(size_t)r * DD + c];
    }

    float acc[4][8];
    float mrow[4], lrow[4];
#pragma unroll
    for (int i = 0; i < 4; i++) {
        mrow[i] = -INFINITY;
        lrow[i] = 0.0f;
#pragma unroll
        for (int j = 0; j < 8; j++) acc[i][j] = 0.0f;
    }

    const float scale = 0.125f;  // 1/sqrt(64)

    for (int kt = 0; kt < SQ; kt += 64) {
        __syncthreads();   // prev PV reads done (and Q visible on iter 0)
        // Load K tile
#pragma unroll
        for (int t = 0; t < 32; t++) {
            int i = tid + t * 128;
            int r = i >> 6, c = i & 63;
            KVs[SKEW(r, c)] = Kg[(size_t)(kt + r) * DD + c];
        }
        __syncthreads();

        // Scores: sc[i][j] = Q[r0+i] . K[cg+8j]
        float sc[4][8];
#pragma unroll
        for (int i = 0; i < 4; i++)
#pragma unroll
            for (int j = 0; j < 8; j++) sc[i][j] = 0.0f;

#pragma unroll 4
        for (int d = 0; d < 64; d++) {
            float q[4], k[8];
#pragma unroll
            for (int i = 0; i < 4; i++) q[i] = Qs[SKEW(r0 + i, d)];
#pragma unroll
            for (int j = 0; j < 8; j++) k[j] = KVs[SKEW(cg + 8 * j, d)];
#pragma unroll
            for (int i = 0; i < 4; i++)
#pragma unroll
                for (int j = 0; j < 8; j++) sc[i][j] += q[i] * k[j];
        }

        // Online softmax update per row
#pragma unroll
        for (int i = 0; i < 4; i++) {
            float tmax = -INFINITY;
#pragma unroll
            for (int j = 0; j < 8; j++) {
                sc[i][j] *= scale;
                tmax = fmaxf(tmax, sc[i][j]);
            }
#pragma unroll
            for (int o = 1; o < 8; o <<= 1)
                tmax = fmaxf(tmax, __shfl_xor_sync(0xffffffffu, tmax, o));
            float mnew = fmaxf(mrow[i], tmax);
            float alpha = __expf(mrow[i] - mnew);
            mrow[i] = mnew;
            float ls = 0.0f;
#pragma unroll
            for (int j = 0; j < 8; j++) {
                float p = __expf(sc[i][j] - mnew);
                sc[i][j] = p;
                ls += p;
            }
#pragma unroll
            for (int o = 1; o < 8; o <<= 1)
                ls += __shfl_xor_sync(0xffffffffu, ls, o);
            lrow[i] = lrow[i] * alpha + ls;
#pragma unroll
            for (int j = 0; j < 8; j++) acc[i][j] *= alpha;
            // publish P
#pragma unroll
            for (int j = 0; j < 8; j++) Ps[SKEW(r0 + i, cg + 8 * j)] = sc[i][j];
        }
        __syncthreads();   // Ps visible; KVs free

        // Load V tile
#pragma unroll
        for (int t = 0; t < 32; t++) {
            int i = tid + t * 128;
            int r = i >> 6, c = i & 63;
            KVs[SKEW(r, c)] = Vg[(size_t)(kt + r) * DD + c];
        }
        __syncthreads();

        // acc += P @ V
#pragma unroll 4
        for (int j = 0; j < 64; j++) {
            float p[4], v[8];
#pragma unroll
            for (int i = 0; i < 4; i++) p[i] = Ps[SKEW(r0 + i, j)];
#pragma unroll
            for (int jj = 0; jj < 8; jj++) v[jj] = KVs[SKEW(j, cg + 8 * jj)];
#pragma unroll
            for (int i = 0; i < 4; i++)
#pragma unroll
                for (int jj = 0; jj < 8; jj++) acc[i][jj] += p[i] * v[jj];
        }
    }

    // Write ctx in [B, S, W] layout (head-concat) for the output projection
    const int b = bh / HH, h = bh % HH;
    float* O = g_ctx + ((size_t)b * SQ + m0) * WW + h * DD;
#pragma unroll
    for (int i = 0; i < 4; i++) {
        float inv = 1.0f / lrow[i];
#pragma unroll
        for (int j = 0; j < 8; j++)
            O[(size_t)(r0 + i) * WW + cg + 8 * j] = acc[i][j] * inv;
    }
}

// ---------------------------------------------------------------------------
// Output projection: out[M x W] = ctx[M x W] @ Wo^T + bo, M = B*S = 8192
// Same 128x64 tile template as qkv_kernel.
// ---------------------------------------------------------------------------
__global__ __launch_bounds__(128) void outproj_kernel(
    const float* __restrict__ Wo, const float* __restrict__ bo,
    float* __restrict__ out)
{
    __shared__ float As[16][128];
    __shared__ float Bs[16][64];

    const int m0 = blockIdx.x * 128;
    const int n0 = blockIdx.y * 64;

    const int tid = threadIdx.x;
    const int rg = tid >> 3, cg = tid & 7;
    const int r0 = rg * 8;

    float acc[8][8];
#pragma unroll
    for (int i = 0; i < 8; i++)
#pragma unroll
        for (int j = 0; j < 8; j++) acc[i][j] = 0.0f;

    for (int k0 = 0; k0 < WW; k0 += 16) {
#pragma unroll
        for (int t = 0; t < 16; t++) {
            int i = tid + t * 128;
            int m = i >> 4, kk = i & 15;
            As[kk][m] = g_ctx[(size_t)(m0 + m) * WW + k0 + kk];
        }
#pragma unroll
        for (int t = 0; t < 8; t++) {
            int i = tid + t * 128;
            int n = i >> 4, kk = i & 15;
            Bs[kk][n] = Wo[(size_t)(n0 + n) * WW + k0 + kk];
        }
        __syncthreads();
#pragma unroll
        for (int kk = 0; kk < 16; kk++) {
            float a[8], bb[8];
#pragma unroll
            for (int i = 0; i < 8; i++) a[i] = As[kk][r0 + i];
#pragma unroll
            for (int j = 0; j < 8; j++) bb[j] = Bs[kk][cg + 8 * j];
#pragma unroll
            for (int i = 0; i < 8; i++)
#pragma unroll
                for (int j = 0; j < 8; j++) acc[i][j] += a[i] * bb[j];
        }
        __syncthreads();
    }

#pragma unroll
    for (int i = 0; i < 8; i++)
#pragma unroll
        for (int j = 0; j < 8; j++) {
            int n = n0 + cg + 8 * j;
            out[(size_t)(m0 + r0 + i) * WW + n] = acc[i][j] + bo[n];
        }
}

// ---------------------------------------------------------------------------
extern "C" void kernel_launch(void* const* d_in, const int* in_sizes, int n_in,
                              void* d_out, int out_size)
{
    (void)in_sizes; (void)n_in; (void)out_size;
    const float* x  = (const float*)d_in[0];
    const float* Wq = (const float*)d_in[1];
    const float* Wk = (const float*)d_in[2];
    const float* Wv = (const float*)d_in[3];
    const float* bq = (const float*)d_in[4];
    const float* bk = (const float*)d_in[5];
    const float* bv = (const float*)d_in[6];
    const float* Wo = (const float*)d_in[7];
    const float* bo = (const float*)d_in[8];
    float* out = (float*)d_out;

    qkv_kernel<<<dim3(SQ / 128, BQ * HH, 3), 128>>>(x, Wq, Wk, Wv, bq, bk, bv);
    attn_kernel<<<dim3(SQ / 64, BQ * HH), 128, 3 * 4096 * sizeof(float)>>>();
    outproj_kernel<<<dim3((BQ * SQ) / 128, WW / 64), 128>>>(Wo, bo, out);
}

// round 2
// speedup vs baseline: 3.7813x; 3.7813x over previous
#include <cuda_runtime.h>
#include <math.h>

#define BQ 4
#define SQ 2048
#define WW 768
#define HH 12
#define DD 64

// Scratch (device globals: allocation-free contract)
__device__ float g_q[(size_t)BQ*HH*SQ*DD];
__device__ float g_k[(size_t)BQ*HH*SQ*DD];
__device__ float g_v[(size_t)BQ*HH*SQ*DD];
__device__ float g_ctx[(size_t)BQ*SQ*WW];

// ---------------------------------------------------------------------------
// tf32 helpers
// ---------------------------------------------------------------------------
__device__ __forceinline__ unsigned f2t(float f) {
    unsigned r;
    asm("cvt.rna.tf32.f32 %0, %1;" : "=r"(r) : "f"(f));
    return r;
}

// D += A(16x8, tf32 row) * B(8x8, tf32 col), fp32 accum
__device__ __forceinline__ void mma8(float* d, const unsigned* a, unsigned b0, unsigned b1) {
    asm volatile(
        "mma.sync.aligned.m16n8k8.row.col.f32.tf32.tf32.f32 "
        "{%0,%1,%2,%3}, {%4,%5,%6,%7}, {%8,%9}, {%0,%1,%2,%3};"
        : "+f"(d[0]), "+f"(d[1]), "+f"(d[2]), "+f"(d[3])
        : "r"(a[0]), "r"(a[1]), "r"(a[2]), "r"(a[3]), "r"(b0), "r"(b1));
}

// Fragment layouts (m16n8k8 tf32), lane = 32 threads, g = lane>>2, t = lane&3:
//  A: a0=(g,t) a1=(g+8,t) a2=(g,t+4) a3=(g+8,t+4)      (row, col=k)
//  B: b0=(k=t, n=g) b1=(k=t+4, n=g)
//  C: c0=(g,2t) c1=(g,2t+1) c2=(g+8,2t) c3=(g+8,2t+1)

// ---------------------------------------------------------------------------
// QKV projection via tf32 mma: C[S x 64] = x[b] (S x W) @ Wm[h] (W x 64) + bias
// Block: 128 x 64, 8 warps (warp = 32x32), BK = 32.
// ---------------------------------------------------------------------------
__global__ __launch_bounds__(256) void qkv_mma(
    const float* __restrict__ x,
    const float* __restrict__ Wq, const float* __restrict__ Wk, const float* __restrict__ Wv,
    const float* __restrict__ bq, const float* __restrict__ bk, const float* __restrict__ bv)
{
    __shared__ unsigned As[128 * 36];  // [m][k], pitch 36
    __shared__ unsigned Bs[32 * 72];   // [k][n], pitch 72

    const int mat = blockIdx.z;
    const float* Wm = (mat == 0) ? Wq : (mat == 1) ? Wk : Wv;
    const float* bm = (mat == 0) ? bq : (mat == 1) ? bk : bv;
    float* Om       = (mat == 0) ? g_q : (mat == 1) ? g_k : g_v;

    const int bh = blockIdx.y;
    const int b = bh / HH, h = bh % HH;
    const int m0 = blockIdx.x * 128;

    const float* A  = x  + (size_t)b * SQ * WW;
    const float* Bw = Wm + (size_t)h * WW * DD;

    const int tid = threadIdx.x;
    const int w = tid >> 5, lane = tid & 31;
    const int g = lane >> 2, t = lane & 3;
    const int wr = w >> 1, wc = w & 1;

    float acc[2][4][4];
#pragma unroll
    for (int mt = 0; mt < 2; mt++)
#pragma unroll
        for (int nt = 0; nt < 4; nt++)
#pragma unroll
            for (int i = 0; i < 4; i++) acc[mt][nt][i] = 0.0f;

    const int ar = tid >> 3, ak = (tid & 7) * 4;   // As staging coords
    const int bkr = tid >> 3, bnc = (tid & 7) * 8; // Bs staging coords

    for (int k0 = 0; k0 < WW; k0 += 32) {
        // Stage A tile 128x32 (converted to tf32)
#pragma unroll
        for (int r = 0; r < 4; r++) {
            float4 v = *(const float4*)&A[(size_t)(m0 + ar + 32 * r) * WW + k0 + ak];
            uint4 u = make_uint4(f2t(v.x), f2t(v.y), f2t(v.z), f2t(v.w));
            *(uint4*)&As[(ar + 32 * r) * 36 + ak] = u;
        }
        // Stage B tile 32x64
        {
            float4 v0 = *(const float4*)&Bw[(size_t)(k0 + bkr) * DD + bnc];
            float4 v1 = *(const float4*)&Bw[(size_t)(k0 + bkr) * DD + bnc + 4];
            *(uint4*)&Bs[bkr * 72 + bnc]     = make_uint4(f2t(v0.x), f2t(v0.y), f2t(v0.z), f2t(v0.w));
            *(uint4*)&Bs[bkr * 72 + bnc + 4] = make_uint4(f2t(v1.x), f2t(v1.y), f2t(v1.z), f2t(v1.w));
        }
        __syncthreads();

#pragma unroll
        for (int kk = 0; kk < 4; kk++) {
            unsigned a[2][4], bf[4][2];
#pragma unroll
            for (int mt = 0; mt < 2; mt++) {
                int mr = wr * 32 + mt * 16;
                a[mt][0] = As[(mr + g) * 36 + kk * 8 + t];
                a[mt][1] = As[(mr + g + 8) * 36 + kk * 8 + t];
                a[mt][2] = As[(mr + g) * 36 + kk * 8 + t + 4];
                a[mt][3] = As[(mr + g + 8) * 36 + kk * 8 + t + 4];
            }
#pragma unroll
            for (int nt = 0; nt < 4; nt++) {
                int nc = wc * 32 + nt * 8;
                bf[nt][0] = Bs[(kk * 8 + t) * 72 + nc + g];
                bf[nt][1] = Bs[(kk * 8 + t + 4) * 72 + nc + g];
            }
#pragma unroll
            for (int mt = 0; mt < 2; mt++)
#pragma unroll
                for (int nt = 0; nt < 4; nt++)
                    mma8(acc[mt][nt], a[mt], bf[nt][0], bf[nt][1]);
        }
        __syncthreads();
    }

    // Epilogue: add bias, write [bh][S][64]
#pragma unroll
    for (int mt = 0; mt < 2; mt++) {
        int row = m0 + wr * 32 + mt * 16 + g;
#pragma unroll
        for (int nt = 0; nt < 4; nt++) {
            int col = wc * 32 + nt * 8 + 2 * t;
            float bias0 = bm[h * DD + col], bias1 = bm[h * DD + col + 1];
            float2 v0 = make_float2(acc[mt][nt][0] + bias0, acc[mt][nt][1] + bias1);
            float2 v1 = make_float2(acc[mt][nt][2] + bias0, acc[mt][nt][3] + bias1);
            *(float2*)&Om[((size_t)bh * SQ + row) * DD + col]     = v0;
            *(float2*)&Om[((size_t)bh * SQ + row + 8) * DD + col] = v1;
        }
    }
}

// ---------------------------------------------------------------------------
// Flash attention via tf32 mma. Block = 64 q-rows of one (b,h), 4 warps.
// Warp owns 16 q-rows. Q fragments in registers (pre-scaled). K, V^T, P
// staged in shared as tf32 with pitch 68 (conflict-free fragment loads).
// ---------------------------------------------------------------------------
#define APITCH 68

__global__ __launch_bounds__(128) void attn_mma()
{
    extern __shared__ unsigned smA[];
    unsigned* Ks = smA;                 // [kv][d]  64 x pitch68
    unsigned* Vt = smA + 64 * APITCH;   // [d][kv]  64 x pitch68
    unsigned* Ps = smA + 128 * APITCH;  // [q][kv]  64 x pitch68

    const int bh = blockIdx.y;
    const int m0 = blockIdx.x * 64;
    const float* Qg = g_q + ((size_t)bh * SQ + m0) * DD;
    const float* Kg = g_k + (size_t)bh * SQ * DD;
    const float* Vg = g_v + (size_t)bh * SQ * DD;

    const int tid = threadIdx.x;
    const int w = tid >> 5, lane = tid & 31;
    const int g = lane >> 2, t = lane & 3;
    const int qr = w * 16 + g;  // local q row (lo); +8 = hi

    // Q fragments, pre-scaled by 1/sqrt(D) = 0.125
    unsigned qa[8][4];
#pragma unroll
    for (int kk = 0; kk < 8; kk++) {
        qa[kk][0] = f2t(0.125f * Qg[(size_t)qr * DD + kk * 8 + t]);
        qa[kk][1] = f2t(0.125f * Qg[(size_t)(qr + 8) * DD + kk * 8 + t]);
        qa[kk][2] = f2t(0.125f * Qg[(size_t)qr * DD + kk * 8 + t + 4]);
        qa[kk][3] = f2t(0.125f * Qg[(size_t)(qr + 8) * DD + kk * 8 + t + 4]);
    }

    float o[8][4];
#pragma unroll
    for (int j = 0; j < 8; j++)
#pragma unroll
        for (int i = 0; i < 4; i++) o[j][i] = 0.0f;
    float m_lo = -INFINITY, m_hi = -INFINITY, l_lo = 0.0f, l_hi = 0.0f;

    for (int kt = 0; kt < SQ; kt += 64) {
        __syncthreads();  // previous iter's Ks/Vt reads complete
        // Stage K and V^T (tf32)
#pragma unroll 4
        for (int i = tid; i < 4096; i += 128) {
            int r = i >> 6, c = i & 63;
            float kvf = Kg[(size_t)(kt + r) * DD + c];
            float vvf = Vg[(size_t)(kt + r) * DD + c];
            Ks[r * APITCH + c] = f2t(kvf);
            Vt[c * APITCH + r] = f2t(vvf);
        }
        __syncthreads();

        // Scores S = (Q*scale) . K^T : per warp 16 x 64
        float s[8][4];
#pragma unroll
        for (int j = 0; j < 8; j++)
#pragma unroll
            for (int i = 0; i < 4; i++) s[j][i] = 0.0f;
#pragma unroll
        for (int kk = 0; kk < 8; kk++) {
#pragma unroll
            for (int j = 0; j < 8; j++) {
                unsigned b0 = Ks[(j * 8 + g) * APITCH + kk * 8 + t];
                unsigned b1 = Ks[(j * 8 + g) * APITCH + kk * 8 + t + 4];
                mma8(s[j], qa[kk], b0, b1);
            }
        }

        // Online softmax (rows qr and qr+8)
        float mx_lo = -INFINITY, mx_hi = -INFINITY;
#pragma unroll
        for (int j = 0; j < 8; j++) {
            mx_lo = fmaxf(mx_lo, fmaxf(s[j][0], s[j][1]));
            mx_hi = fmaxf(mx_hi, fmaxf(s[j][2], s[j][3]));
        }
#pragma unroll
        for (int off = 1; off < 4; off <<= 1) {
            mx_lo = fmaxf(mx_lo, __shfl_xor_sync(0xffffffffu, mx_lo, off));
            mx_hi = fmaxf(mx_hi, __shfl_xor_sync(0xffffffffu, mx_hi, off));
        }
        float mn_lo = fmaxf(m_lo, mx_lo), mn_hi = fmaxf(m_hi, mx_hi);
        float al_lo = __expf(m_lo - mn_lo), al_hi = __expf(m_hi - mn_hi);
        m_lo = mn_lo; m_hi = mn_hi;

        float sum_lo = 0.0f, sum_hi = 0.0f;
#pragma unroll
        for (int j = 0; j < 8; j++) {
            float p0 = __expf(s[j][0] - mn_lo);
            float p1 = __expf(s[j][1] - mn_lo);
            float p2 = __expf(s[j][2] - mn_hi);
            float p3 = __expf(s[j][3] - mn_hi);
            sum_lo += p0 + p1;
            sum_hi += p2 + p3;
            int col = j * 8 + 2 * t;
            *(uint2*)&Ps[qr * APITCH + col]       = make_uint2(f2t(p0), f2t(p1));
            *(uint2*)&Ps[(qr + 8) * APITCH + col] = make_uint2(f2t(p2), f2t(p3));
            o[j][0] *= al_lo; o[j][1] *= al_lo;
            o[j][2] *= al_hi; o[j][3] *= al_hi;
        }
#pragma unroll
        for (int off = 1; off < 4; off <<= 1) {
            sum_lo += __shfl_xor_sync(0xffffffffu, sum_lo, off);
            sum_hi += __shfl_xor_sync(0xffffffffu, sum_hi, off);
        }
        l_lo = l_lo * al_lo + sum_lo;
        l_hi = l_hi * al_hi + sum_hi;

        __syncwarp();  // Ps rows are warp-private; make stores visible in-warp

        // O += P . V  (k-dim = kv, n-dim = d)
#pragma unroll
        for (int kk = 0; kk < 8; kk++) {
            unsigned pa[4];
            pa[0] = Ps[qr * APITCH + kk * 8 + t];
            pa[1] = Ps[(qr + 8) * APITCH + kk * 8 + t];
            pa[2] = Ps[qr * APITCH + kk * 8 + t + 4];
            pa[3] = Ps[(qr + 8) * APITCH + kk * 8 + t + 4];
#pragma unroll
            for (int j = 0; j < 8; j++) {
                unsigned b0 = Vt[(j * 8 + g) * APITCH + kk * 8 + t];
                unsigned b1 = Vt[(j * 8 + g) * APITCH + kk * 8 + t + 4];
                mma8(o[j], pa, b0, b1);
            }
        }
        __syncwarp();  // all Ps reads done before next iteration overwrites
    }

    // Epilogue: normalize, write ctx in [B, S, W] head-concat layout
    const int b = bh / HH, h = bh % HH;
    const float il_lo = 1.0f / l_lo, il_hi = 1.0f / l_hi;
    const int row_lo = m0 + w * 16 + g;
    float* O = g_ctx + ((size_t)b * SQ + row_lo) * WW + h * DD;
#pragma unroll
    for (int j = 0; j < 8; j++) {
        int col = j * 8 + 2 * t;
        *(float2*)&O[col] = make_float2(o[j][0] * il_lo, o[j][1] * il_lo);
        *(float2*)&O[8 * WW + col] = make_float2(o[j][2] * il_hi, o[j][3] * il_hi);
    }
}

// ---------------------------------------------------------------------------
// Output projection via tf32 mma: out[M x W] = ctx @ Wo^T + bo, M = 8192
// Block 128 x 64, 8 warps, BK = 32. B[k][n] = Wo[n][k] (staged transposed).
// ---------------------------------------------------------------------------
__global__ __launch_bounds__(256) void outproj_mma(
    const float* __restrict__ Wo, const float* __restrict__ bo,
    float* __restrict__ out)
{
    __shared__ unsigned As[128 * 36];  // [m][k] pitch 36
    __shared__ unsigned Bs[32 * 73];   // [k][n] pitch 73

    const int m0 = blockIdx.x * 128;
    const int n0 = blockIdx.y * 64;

    const int tid = threadIdx.x;
    const int w = tid >> 5, lane = tid & 31;
    const int g = lane >> 2, t = lane & 3;
    const int wr = w >> 1, wc = w & 1;

    float acc[2][4][4];
#pragma unroll
    for (int mt = 0; mt < 2; mt++)
#pragma unroll
        for (int nt = 0; nt < 4; nt++)
#pragma unroll
            for (int i = 0; i < 4; i++) acc[mt][nt][i] = 0.0f;

    const int ar = tid >> 3, ak = (tid & 7) * 4;
    const int bn = tid >> 2, bkc = (tid & 3) * 8;  // Wo row n, k-chunk of 8

    for (int k0 = 0; k0 < WW; k0 += 32) {
#pragma unroll
        for (int r = 0; r < 4; r++) {
            float4 v = *(const float4*)&g_ctx[(size_t)(m0 + ar + 32 * r) * WW + k0 + ak];
            *(uint4*)&As[(ar + 32 * r) * 36 + ak] =
                make_uint4(f2t(v.x), f2t(v.y), f2t(v.z), f2t(v.w));
        }
        {
            float4 v0 = *(const float4*)&Wo[(size_t)(n0 + bn) * WW + k0 + bkc];
            float4 v1 = *(const float4*)&Wo[(size_t)(n0 + bn) * WW + k0 + bkc + 4];
            Bs[(bkc + 0) * 73 + bn] = f2t(v0.x);
            Bs[(bkc + 1) * 73 + bn] = f2t(v0.y);
            Bs[(bkc + 2) * 73 + bn] = f2t(v0.z);
            Bs[(bkc + 3) * 73 + bn] = f2t(v0.w);
            Bs[(bkc + 4) * 73 + bn] = f2t(v1.x);
            Bs[(bkc + 5) * 73 + bn] = f2t(v1.y);
            Bs[(bkc + 6) * 73 + bn] = f2t(v1.z);
            Bs[(bkc + 7) * 73 + bn] = f2t(v1.w);
        }
        __syncthreads();

#pragma unroll
        for (int kk = 0; kk < 4; kk++) {
            unsigned a[2][4], bf[4][2];
#pragma unroll
            for (int mt = 0; mt < 2; mt++) {
                int mr = wr * 32 + mt * 16;
                a[mt][0] = As[(mr + g) * 36 + kk * 8 + t];
                a[mt][1] = As[(mr + g + 8) * 36 + kk * 8 + t];
                a[mt][2] = As[(mr + g) * 36 + kk * 8 + t + 4];
                a[mt][3] = As[(mr + g + 8) * 36 + kk * 8 + t + 4];
            }
#pragma unroll
            for (int nt = 0; nt < 4; nt++) {
                int nc = wc * 32 + nt * 8;
                bf[nt][0] = Bs[(kk * 8 + t) * 73 + nc + g];
                bf[nt][1] = Bs[(kk * 8 + t + 4) * 73 + nc + g];
            }
#pragma unroll
            for (int mt = 0; mt < 2; mt++)
#pragma unroll
                for (int nt = 0; nt < 4; nt++)
                    mma8(acc[mt][nt], a[mt], bf[nt][0], bf[nt][1]);
        }
        __syncthreads();
    }

#pragma unroll
    for (int mt = 0; mt < 2; mt++) {
        int row = m0 + wr * 32 + mt * 16 + g;
#pragma unroll
        for (int nt = 0; nt < 4; nt++) {
            int col = n0 + wc * 32 + nt * 8 + 2 * t;
            float bias0 = bo[col], bias1 = bo[col + 1];
            *(float2*)&out[(size_t)row * WW + col] =
                make_float2(acc[mt][nt][0] + bias0, acc[mt][nt][1] + bias1);
            *(float2*)&out[(size_t)(row + 8) * WW + col] =
                make_float2(acc[mt][nt][2] + bias0, acc[mt][nt][3] + bias1);
        }
    }
}

// ---------------------------------------------------------------------------
extern "C" void kernel_launch(void* const* d_in, const int* in_sizes, int n_in,
                              void* d_out, int out_size)
{
    (void)in_sizes; (void)n_in; (void)out_size;
    const float* x  = (const float*)d_in[0];
    const float* Wq = (const float*)d_in[1];
    const float* Wk = (const float*)d_in[2];
    const float* Wv = (const float*)d_in[3];
    const float* bq = (const float*)d_in[4];
    const float* bk = (const float*)d_in[5];
    const float* bv = (const float*)d_in[6];
    const float* Wo = (const float*)d_in[7];
    const float* bo = (const float*)d_in[8];
    float* out = (float*)d_out;

    static bool attr_done = false;
    if (!attr_done) {
        cudaFuncSetAttribute(attn_mma, cudaFuncAttributeMaxDynamicSharedMemorySize,
                             192 * APITCH * 4);
        attr_done = true;
    }

    qkv_mma<<<dim3(SQ / 128, BQ * HH, 3), 256>>>(x, Wq, Wk, Wv, bq, bk, bv);
    attn_mma<<<dim3(SQ / 64, BQ * HH), 128, 192 * APITCH * 4>>>();
    outproj_mma<<<dim3((BQ * SQ) / 128, WW / 64), 256>>>(Wo, bo, out);
}

// round 3
// speedup vs baseline: 10.0769x; 2.6649x over previous
#include <cuda_runtime.h>
#include <cuda_fp16.h>
#include <math.h>

#define BQ 4
#define SQ 2048
#define WW 768
#define HH 12
#define DD 64

// fp16 scratch (device globals: allocation-free contract)
__device__ __half g_xh[(size_t)BQ*SQ*WW];
__device__ __half g_wqh[(size_t)HH*WW*DD];
__device__ __half g_wkh[(size_t)HH*WW*DD];
__device__ __half g_wvh[(size_t)HH*WW*DD];
__device__ __half g_woh[(size_t)WW*WW];
__device__ __half g_qh[(size_t)BQ*HH*SQ*DD];
__device__ __half g_kh[(size_t)BQ*HH*SQ*DD];
__device__ __half g_vh[(size_t)BQ*HH*SQ*DD];
__device__ __half g_ctxh[(size_t)BQ*SQ*WW];

// ---------------------------------------------------------------------------
// helpers
// ---------------------------------------------------------------------------
__device__ __forceinline__ unsigned sptr(const void* p) {
    return (unsigned)__cvta_generic_to_shared(p);
}
__device__ __forceinline__ void cp16(unsigned dst, const void* src) {
    asm volatile("cp.async.cg.shared.global [%0], [%1], 16;" :: "r"(dst), "l"(src));
}
__device__ __forceinline__ void cp_commit() { asm volatile("cp.async.commit_group;"); }
template<int N> __device__ __forceinline__ void cp_wait() {
    asm volatile("cp.async.wait_group %0;" :: "n"(N));
}
__device__ __forceinline__ void ldsm4(unsigned addr, unsigned& r0, unsigned& r1,
                                      unsigned& r2, unsigned& r3) {
    asm volatile("ldmatrix.sync.aligned.m8n8.x4.shared.b16 {%0,%1,%2,%3}, [%4];"
                 : "=r"(r0), "=r"(r1), "=r"(r2), "=r"(r3) : "r"(addr));
}
__device__ __forceinline__ void ldsm4t(unsigned addr, unsigned& r0, unsigned& r1,
                                       unsigned& r2, unsigned& r3) {
    asm volatile("ldmatrix.sync.aligned.m8n8.x4.trans.shared.b16 {%0,%1,%2,%3}, [%4];"
                 : "=r"(r0), "=r"(r1), "=r"(r2), "=r"(r3) : "r"(addr));
}
// D += A(16x16 f16) * B(16x8 f16), fp32 accum
__device__ __forceinline__ void mma16(float* d, const unsigned* a, unsigned b0, unsigned b1) {
    asm volatile(
        "mma.sync.aligned.m16n8k16.row.col.f32.f16.f16.f32 "
        "{%0,%1,%2,%3}, {%4,%5,%6,%7}, {%8,%9}, {%0,%1,%2,%3};"
        : "+f"(d[0]), "+f"(d[1]), "+f"(d[2]), "+f"(d[3])
        : "r"(a[0]), "r"(a[1]), "r"(a[2]), "r"(a[3]), "r"(b0), "r"(b1));
}
__device__ __forceinline__ float fexp2(float x) {
    float y; asm("ex2.approx.ftz.f32 %0, %1;" : "=f"(y) : "f"(x)); return y;
}
__device__ __forceinline__ unsigned packh2(float a, float b) {
    __half2 h = __floats2half2_rn(a, b);
    return *(unsigned*)&h;
}

// ---------------------------------------------------------------------------
// Prepass: fp32 -> fp16 conversion of x and weights (once per launch)
// ---------------------------------------------------------------------------
__global__ __launch_bounds__(256) void prepass(
    const float* __restrict__ x, const float* __restrict__ Wq,
    const float* __restrict__ Wk, const float* __restrict__ Wv,
    const float* __restrict__ Wo)
{
    const int tid = blockIdx.x * blockDim.x + threadIdx.x;
    const int stride = gridDim.x * blockDim.x;
    // x: vectorized float4 -> half2 pairs
    const size_t nx4 = (size_t)BQ * SQ * WW / 4;
    __half2* xo = (__half2*)g_xh;
    for (size_t i = tid; i < nx4; i += stride) {
        float4 v = ((const float4*)x)[i];
        xo[2 * i]     = __floats2half2_rn(v.x, v.y);
        xo[2 * i + 1] = __floats2half2_rn(v.z, v.w);
    }
    const int nw = HH * WW * DD;
    for (int i = tid; i < nw; i += stride) {
        g_wqh[i] = __float2half(Wq[i]);
        g_wkh[i] = __float2half(Wk[i]);
        g_wvh[i] = __float2half(Wv[i]);
    }
    const int no = WW * WW;
    for (int i = tid; i < no; i += stride) g_woh[i] = __float2half(Wo[i]);
}

// ---------------------------------------------------------------------------
// QKV projection (fp16 mma + ldmatrix + cp.async double-buffer)
// Block 128x64, 8 warps (4 m-groups x 2 n-groups), BK=64.
// ---------------------------------------------------------------------------
__global__ __launch_bounds__(256) void qkv_h(
    const float* __restrict__ bqp, const float* __restrict__ bkp,
    const float* __restrict__ bvp)
{
    extern __shared__ __align__(16) __half sh[];
    __half* As = sh;                 // [2][128*72]
    __half* Bs = sh + 2 * 128 * 72;  // [2][64*72]

    const int mat = blockIdx.z;
    const __half* Wmh = (mat == 0) ? g_wqh : (mat == 1) ? g_wkh : g_wvh;
    const float* bm   = (mat == 0) ? bqp : (mat == 1) ? bkp : bvp;
    __half* Om        = (mat == 0) ? g_qh : (mat == 1) ? g_kh : g_vh;

    const int bh = blockIdx.y;
    const int b = bh / HH, h = bh % HH;
    const int m0 = blockIdx.x * 128;
    const __half* Ax = g_xh + (size_t)b * SQ * WW;
    const __half* Bw = Wmh + (size_t)h * WW * DD;

    const int tid = threadIdx.x, w = tid >> 5, l = tid & 31;
    const int g = l >> 2, t = l & 3;
    const int wr = w >> 1, wc = w & 1;

    const unsigned a_row = (l & 15), a_colp = (l >> 4) * 8;
    const unsigned b_rowp = (l & 7) + 8 * ((l >> 3) & 1), b_colp = 8 * (l >> 4);

    float acc[2][4][4];
#pragma unroll
    for (int mt = 0; mt < 2; mt++)
#pragma unroll
        for (int nt = 0; nt < 4; nt++)
#pragma unroll
            for (int i = 0; i < 4; i++) acc[mt][nt][i] = 0.0f;

    auto stageA = [&](int buf, int k0) {
        unsigned base = sptr(As + buf * 128 * 72);
#pragma unroll
        for (int i = 0; i < 4; i++) {
            int j = tid + i * 256, r = j >> 3, c = j & 7;
            cp16(base + (r * 72 + c * 8) * 2, Ax + (size_t)(m0 + r) * WW + k0 + c * 8);
        }
    };
    auto stageB = [&](int buf, int k0) {
        unsigned base = sptr(Bs + buf * 64 * 72);
#pragma unroll
        for (int i = 0; i < 2; i++) {
            int j = tid + i * 256, r = j >> 3, c = j & 7;
            cp16(base + (r * 72 + c * 8) * 2, Bw + (size_t)(k0 + r) * DD + c * 8);
        }
    };

    stageA(0, 0); stageB(0, 0); cp_commit();
    const int NIT = WW / 64;  // 12
    for (int it = 0; it < NIT; ++it) {
        int cur = it & 1;
        if (it + 1 < NIT) {
            stageA(cur ^ 1, (it + 1) * 64); stageB(cur ^ 1, (it + 1) * 64);
            cp_commit(); cp_wait<1>();
        } else cp_wait<0>();
        __syncthreads();

        unsigned Abase = sptr(As + cur * 128 * 72);
        unsigned Bbase = sptr(Bs + cur * 64 * 72);
#pragma unroll
        for (int kk = 0; kk < 4; ++kk) {
            unsigned a[2][4], bb[2][4];
#pragma unroll
            for (int mt = 0; mt < 2; ++mt)
                ldsm4(Abase + ((wr * 32 + mt * 16 + a_row) * 72 + kk * 16 + a_colp) * 2,
                      a[mt][0], a[mt][1], a[mt][2], a[mt][3]);
#pragma unroll
            for (int np = 0; np < 2; ++np)
                ldsm4t(Bbase + ((kk * 16 + b_rowp) * 72 + wc * 32 + np * 16 + b_colp) * 2,
                       bb[np][0], bb[np][1], bb[np][2], bb[np][3]);
#pragma unroll
            for (int mt = 0; mt < 2; ++mt)
#pragma unroll
                for (int nt = 0; nt < 4; ++nt)
                    mma16(acc[mt][nt], a[mt], bb[nt >> 1][(nt & 1) * 2],
                          bb[nt >> 1][(nt & 1) * 2 + 1]);
        }
        __syncthreads();
    }

    __half* O = Om + (size_t)bh * SQ * DD;
#pragma unroll
    for (int mt = 0; mt < 2; ++mt) {
        int row = m0 + wr * 32 + mt * 16 + g;
#pragma unroll
        for (int nt = 0; nt < 4; ++nt) {
            int col = wc * 32 + nt * 8 + 2 * t;
            float b0f = bm[h * DD + col], b1f = bm[h * DD + col + 1];
            *(unsigned*)&O[(size_t)row * DD + col] =
                packh2(acc[mt][nt][0] + b0f, acc[mt][nt][1] + b1f);
            *(unsigned*)&O[(size_t)(row + 8) * DD + col] =
                packh2(acc[mt][nt][2] + b0f, acc[mt][nt][3] + b1f);
        }
    }
}

// ---------------------------------------------------------------------------
// Flash attention, fp16 mma. Block = 128 q-rows, 8 warps (16 rows each).
// P kept entirely in registers (QK C-frag == PV A-frag layout).
// ---------------------------------------------------------------------------
__global__ __launch_bounds__(256) void attn_h()
{
    extern __shared__ __align__(16) __half sh[];
    __half* Qs = sh;                           // 128*72
    __half* Ks = sh + 128 * 72;                // [2][64*72]
    __half* Vs = sh + 128 * 72 + 2 * 64 * 72;  // [2][64*72]

    const int bh = blockIdx.y, b = bh / HH, h = bh % HH;
    const int m0 = blockIdx.x * 128;
    const __half* Qg = g_qh + ((size_t)bh * SQ + m0) * DD;
    const __half* Kg = g_kh + (size_t)bh * SQ * DD;
    const __half* Vg = g_vh + (size_t)bh * SQ * DD;

    const int tid = threadIdx.x, w = tid >> 5, l = tid & 31;
    const int g = l >> 2, t = l & 3;

    // stage Q (128x64)
    {
        unsigned base = sptr(Qs);
#pragma unroll
        for (int i = 0; i < 4; i++) {
            int j = tid + i * 256, r = j >> 3, c = j & 7;
            cp16(base + (r * 72 + c * 8) * 2, Qg + (size_t)r * DD + c * 8);
        }
    }
    auto stageKV = [&](int buf, int kt) {
        unsigned kb = sptr(Ks + buf * 64 * 72), vb = sptr(Vs + buf * 64 * 72);
#pragma unroll
        for (int i = 0; i < 2; i++) {
            int j = tid + i * 256, r = j >> 3, c = j & 7;
            cp16(kb + (r * 72 + c * 8) * 2, Kg + (size_t)(kt + r) * DD + c * 8);
            cp16(vb + (r * 72 + c * 8) * 2, Vg + (size_t)(kt + r) * DD + c * 8);
        }
    };
    stageKV(0, 0); cp_commit();

    const unsigned a_row = (l & 15), a_colp = (l >> 4) * 8;                 // Q (A, non-trans)
    const unsigned k_row = (l & 7) + 8 * (l >> 4), k_colp = 8 * ((l >> 3) & 1);  // K (B, non-trans)
    const unsigned v_row = (l & 7) + 8 * ((l >> 3) & 1), v_colp = 8 * (l >> 4);  // V (B, trans)

    unsigned qa[4][4];
    float o[8][4];
#pragma unroll
    for (int j = 0; j < 8; j++)
#pragma unroll
        for (int i = 0; i < 4; i++) o[j][i] = 0.0f;
    float m_lo = -INFINITY, m_hi = -INFINITY, l_lo = 0.0f, l_hi = 0.0f;
    const float C2 = 0.125f * 1.4426950408889634f;  // scale * log2(e)

    const int NIT = SQ / 64;  // 32
    for (int it = 0; it < NIT; ++it) {
        int cur = it & 1;
        if (it + 1 < NIT) { stageKV(cur ^ 1, (it + 1) * 64); cp_commit(); cp_wait<1>(); }
        else cp_wait<0>();
        __syncthreads();

        if (it == 0) {
            unsigned qb = sptr(Qs);
#pragma unroll
            for (int kk = 0; kk < 4; kk++)
                ldsm4(qb + ((w * 16 + a_row) * 72 + kk * 16 + a_colp) * 2,
                      qa[kk][0], qa[kk][1], qa[kk][2], qa[kk][3]);
        }
        unsigned kbase = sptr(Ks + cur * 64 * 72);
        unsigned vbase = sptr(Vs + cur * 64 * 72);

        // S = Q . K^T  (16 x 64 per warp)
        float s[8][4];
#pragma unroll
        for (int j = 0; j < 8; j++)
#pragma unroll
            for (int i = 0; i < 4; i++) s[j][i] = 0.0f;
#pragma unroll
        for (int kk = 0; kk < 4; kk++)
#pragma unroll
            for (int p = 0; p < 4; p++) {
                unsigned r0, r1, r2, r3;
                ldsm4(kbase + ((p * 16 + k_row) * 72 + kk * 16 + k_colp) * 2, r0, r1, r2, r3);
                mma16(s[2 * p], qa[kk], r0, r1);
                mma16(s[2 * p + 1], qa[kk], r2, r3);
            }

        // online softmax (rows w*16+g and +8); exp2 with folded scale
        float mx_lo = -INFINITY, mx_hi = -INFINITY;
#pragma unroll
        for (int j = 0; j < 8; j++) {
            mx_lo = fmaxf(mx_lo, fmaxf(s[j][0], s[j][1]));
            mx_hi = fmaxf(mx_hi, fmaxf(s[j][2], s[j][3]));
        }
        mx_lo = fmaxf(mx_lo, __shfl_xor_sync(0xffffffffu, mx_lo, 1));
        mx_lo = fmaxf(mx_lo, __shfl_xor_sync(0xffffffffu, mx_lo, 2));
        mx_hi = fmaxf(mx_hi, __shfl_xor_sync(0xffffffffu, mx_hi, 1));
        mx_hi = fmaxf(mx_hi, __shfl_xor_sync(0xffffffffu, mx_hi, 2));
        float mn_lo = fmaxf(m_lo, mx_lo), mn_hi = fmaxf(m_hi, mx_hi);
        float al_lo = fexp2((m_lo - mn_lo) * C2), al_hi = fexp2((m_hi - mn_hi) * C2);
        m_lo = mn_lo; m_hi = mn_hi;

        float sum_lo = 0.0f, sum_hi = 0.0f;
#pragma unroll
        for (int j = 0; j < 8; j++) {
            s[j][0] = fexp2((s[j][0] - mn_lo) * C2);
            s[j][1] = fexp2((s[j][1] - mn_lo) * C2);
            s[j][2] = fexp2((s[j][2] - mn_hi) * C2);
            s[j][3] = fexp2((s[j][3] - mn_hi) * C2);
            sum_lo += s[j][0] + s[j][1];
            sum_hi += s[j][2] + s[j][3];
        }
        sum_lo += __shfl_xor_sync(0xffffffffu, sum_lo, 1);
        sum_lo += __shfl_xor_sync(0xffffffffu, sum_lo, 2);
        sum_hi += __shfl_xor_sync(0xffffffffu, sum_hi, 1);
        sum_hi += __shfl_xor_sync(0xffffffffu, sum_hi, 2);
        l_lo = l_lo * al_lo + sum_lo;
        l_hi = l_hi * al_hi + sum_hi;

        // pack P into PV A-fragments (registers only)
        unsigned pa[4][4];
#pragma unroll
        for (int kk = 0; kk < 4; kk++) {
            pa[kk][0] = packh2(s[2 * kk][0], s[2 * kk][1]);
            pa[kk][1] = packh2(s[2 * kk][2], s[2 * kk][3]);
            pa[kk][2] = packh2(s[2 * kk + 1][0], s[2 * kk + 1][1]);
            pa[kk][3] = packh2(s[2 * kk + 1][2], s[2 * kk + 1][3]);
        }
        // rescale accumulators
#pragma unroll
        for (int j = 0; j < 8; j++) {
            o[j][0] *= al_lo; o[j][1] *= al_lo;
            o[j][2] *= al_hi; o[j][3] *= al_hi;
        }
        // O += P . V
#pragma unroll
        for (int kk = 0; kk < 4; kk++)
#pragma unroll
            for (int dp = 0; dp < 4; dp++) {
                unsigned r0, r1, r2, r3;
                ldsm4t(vbase + ((kk * 16 + v_row) * 72 + dp * 16 + v_colp) * 2, r0, r1, r2, r3);
                mma16(o[2 * dp], pa[kk], r0, r1);
                mma16(o[2 * dp + 1], pa[kk], r2, r3);
            }
        __syncthreads();
    }

    // epilogue: normalize, write ctx fp16 in [B,S,W] head-concat layout
    float il_lo = 1.0f / l_lo, il_hi = 1.0f / l_hi;
    int row = m0 + w * 16 + g;
    __half* O = g_ctxh + ((size_t)b * SQ + row) * WW + h * DD;
#pragma unroll
    for (int j = 0; j < 8; j++) {
        int col = j * 8 + 2 * t;
        *(unsigned*)&O[col] = packh2(o[j][0] * il_lo, o[j][1] * il_lo);
        *(unsigned*)&O[(size_t)8 * WW + col] = packh2(o[j][2] * il_hi, o[j][3] * il_hi);
    }
}

// ---------------------------------------------------------------------------
// Output projection: out = ctx @ Wo^T + bo. B staged as [n][k] rows (Wo natural),
// non-trans ldmatrix gives B fragments directly.
// ---------------------------------------------------------------------------
__global__ __launch_bounds__(256) void outproj_h(
    const float* __restrict__ bop, float* __restrict__ out)
{
    extern __shared__ __align__(16) __half sh[];
    __half* As = sh;                 // [2][128*72]
    __half* Bs = sh + 2 * 128 * 72;  // [2][64*72]  rows = n, cols = k

    const int m0 = blockIdx.x * 128;
    const int n0 = blockIdx.y * 64;

    const int tid = threadIdx.x, w = tid >> 5, l = tid & 31;
    const int g = l >> 2, t = l & 3;
    const int wr = w >> 1, wc = w & 1;

    const unsigned a_row = (l & 15), a_colp = (l >> 4) * 8;
    const unsigned b_row = (l & 7) + 8 * (l >> 4), b_colp = 8 * ((l >> 3) & 1);

    float acc[2][4][4];
#pragma unroll
    for (int mt = 0; mt < 2; mt++)
#pragma unroll
        for (int nt = 0; nt < 4; nt++)
#pragma unroll
            for (int i = 0; i < 4; i++) acc[mt][nt][i] = 0.0f;

    auto stageA = [&](int buf, int k0) {
        unsigned base = sptr(As + buf * 128 * 72);
#pragma unroll
        for (int i = 0; i < 4; i++) {
            int j = tid + i * 256, r = j >> 3, c = j & 7;
            cp16(base + (r * 72 + c * 8) * 2, g_ctxh + (size_t)(m0 + r) * WW + k0 + c * 8);
        }
    };
    auto stageB = [&](int buf, int k0) {
        unsigned base = sptr(Bs + buf * 64 * 72);
#pragma unroll
        for (int i = 0; i < 2; i++) {
            int j = tid + i * 256, r = j >> 3, c = j & 7;
            cp16(base + (r * 72 + c * 8) * 2, g_woh + (size_t)(n0 + r) * WW + k0 + c * 8);
        }
    };

    stageA(0, 0); stageB(0, 0); cp_commit();
    const int NIT = WW / 64;
    for (int it = 0; it < NIT; ++it) {
        int cur = it & 1;
        if (it + 1 < NIT) {
            stageA(cur ^ 1, (it + 1) * 64); stageB(cur ^ 1, (it + 1) * 64);
            cp_commit(); cp_wait<1>();
        } else cp_wait<0>();
        __syncthreads();

        unsigned Abase = sptr(As + cur * 128 * 72);
        unsigned Bbase = sptr(Bs + cur * 64 * 72);
#pragma unroll
        for (int kk = 0; kk < 4; ++kk) {
            unsigned a[2][4], bb[2][4];
#pragma unroll
            for (int mt = 0; mt < 2; ++mt)
                ldsm4(Abase + ((wr * 32 + mt * 16 + a_row) * 72 + kk * 16 + a_colp) * 2,
                      a[mt][0], a[mt][1], a[mt][2], a[mt][3]);
#pragma unroll
            for (int np = 0; np < 2; ++np)
                ldsm4(Bbase + ((wc * 32 + np * 16 + b_row) * 72 + kk * 16 + b_colp) * 2,
                      bb[np][0], bb[np][1], bb[np][2], bb[np][3]);
#pragma unroll
            for (int mt = 0; mt < 2; ++mt)
#pragma unroll
                for (int nt = 0; nt < 4; ++nt)
                    mma16(acc[mt][nt], a[mt], bb[nt >> 1][(nt & 1) * 2],
                          bb[nt >> 1][(nt & 1) * 2 + 1]);
        }
        __syncthreads();
    }

#pragma unroll
    for (int mt = 0; mt < 2; ++mt) {
        int row = m0 + wr * 32 + mt * 16 + g;
#pragma unroll
        for (int nt = 0; nt < 4; ++nt) {
            int col = n0 + wc * 32 + nt * 8 + 2 * t;
            float b0f = bop[col], b1f = bop[col + 1];
            *(float2*)&out[(size_t)row * WW + col] =
                make_float2(acc[mt][nt][0] + b0f, acc[mt][nt][1] + b1f);
            *(float2*)&out[(size_t)(row + 8) * WW + col] =
                make_float2(acc[mt][nt][2] + b0f, acc[mt][nt][3] + b1f);
        }
    }
}

// ---------------------------------------------------------------------------
extern "C" void kernel_launch(void* const* d_in, const int* in_sizes, int n_in,
                              void* d_out, int out_size)
{
    (void)in_sizes; (void)n_in; (void)out_size;
    const float* x  = (const float*)d_in[0];
    const float* Wq = (const float*)d_in[1];
    const float* Wk = (const float*)d_in[2];
    const float* Wv = (const float*)d_in[3];
    const float* bq = (const float*)d_in[4];
    const float* bk = (const float*)d_in[5];
    const float* bv = (const float*)d_in[6];
    const float* Wo = (const float*)d_in[7];
    const float* bo = (const float*)d_in[8];
    float* out = (float*)d_out;

    const int SMEM = 55296;
    cudaFuncSetAttribute(qkv_h, cudaFuncAttributeMaxDynamicSharedMemorySize, SMEM);
    cudaFuncSetAttribute(attn_h, cudaFuncAttributeMaxDynamicSharedMemorySize, SMEM);
    cudaFuncSetAttribute(outproj_h, cudaFuncAttributeMaxDynamicSharedMemorySize, SMEM);

    prepass<<<1024, 256>>>(x, Wq, Wk, Wv, Wo);
    qkv_h<<<dim3(SQ / 128, BQ * HH, 3), 256, SMEM>>>(bq, bk, bv);
    attn_h<<<dim3(SQ / 128, BQ * HH), 256, SMEM>>>();
    outproj_h<<<dim3((BQ * SQ) / 128, WW / 64), 256, SMEM>>>(bo, out);
}